// round 5
// baseline (speedup 1.0000x reference)
#include <cuda_runtime.h>

#define NTHREADS 512
#define TS 1032                 // tile row stride (floats)
#define HS 68                   // hbuf row stride
#define WBUF_STRIDE 8448        // per weight buffer (floats): w1 4096 | w2 4096 | b1 128 | b2 64 | pad

#define SM_TILE 0
#define SM_WB   33024           // 32*1032
#define SM_HB   (SM_WB + 2 * WBUF_STRIDE)     // 49920
#define SM_TOTAL (SM_HB + 2 * 2176)           // 54272 floats = 217088 B

typedef unsigned long long u64;
typedef unsigned int u32;

__device__ __forceinline__ u64 pack2(float lo, float hi) {
    u64 r; asm("mov.b64 %0, {%1, %2};" : "=l"(r) : "f"(lo), "f"(hi)); return r;
}
__device__ __forceinline__ void unpack2(u64 v, float& lo, float& hi) {
    asm("mov.b64 {%0, %1}, %2;" : "=f"(lo), "=f"(hi) : "l"(v));
}
__device__ __forceinline__ u64 fma2(u64 a, u64 b, u64 c) {
    u64 d; asm("fma.rn.f32x2 %0, %1, %2, %3;" : "=l"(d) : "l"(a), "l"(b), "l"(c)); return d;
}
__device__ __forceinline__ u32 s2u(const void* p) {
    u32 r;
    asm("{.reg .u64 t; cvta.to.shared.u64 t, %1; cvt.u32.u64 %0, t;}" : "=r"(r) : "l"(p));
    return r;
}
__device__ __forceinline__ void cpa16(u32 dst, const float* src) {
    asm volatile("cp.async.cg.shared.global [%0], [%1], 16;" :: "r"(dst), "l"(src));
}

// in-place 32x32 transpose of each tile row: row[32b+a] <- row[32a+b]
__device__ __forceinline__ void transpose_tile(float* tile, int warp, int lane) {
    const int a2 = lane >> 3;     // 0..3
    const int B  = lane & 7;      // 0..7
    #pragma unroll
    for (int rr = 0; rr < 2; ++rr) {
        float* row = tile + (warp * 2 + rr) * TS;
        float4 v[2][4];
        #pragma unroll
        for (int h = 0; h < 2; ++h) {
            int A = a2 + 4 * h;
            #pragma unroll
            for (int i = 0; i < 4; ++i)
                v[h][i] = *(const float4*)(row + 32 * (4 * A + i) + 4 * B);
        }
        __syncwarp();
        #pragma unroll
        for (int h = 0; h < 2; ++h) {
            int A = a2 + 4 * h;
            // write transposed 4x4 of block (A,B) into block (B,A)
            float4 t;
            #pragma unroll
            for (int i = 0; i < 4; ++i) {
                t.x = ((const float*)&v[h][0])[i];
                t.y = ((const float*)&v[h][1])[i];
                t.z = ((const float*)&v[h][2])[i];
                t.w = ((const float*)&v[h][3])[i];
                *(float4*)(row + 32 * (4 * B + i) + 4 * A) = t;
            }
        }
        __syncwarp();
    }
}

__global__ __launch_bounds__(NTHREADS, 1) void mixer_kernel(
    const float* __restrict__ x,
    const float* __restrict__ W1a, const float* __restrict__ B1a,
    const float* __restrict__ W2a, const float* __restrict__ B2a,
    const float* __restrict__ W1b, const float* __restrict__ B1b,
    const float* __restrict__ W2b, const float* __restrict__ B2b,
    float* __restrict__ out)
{
    extern __shared__ float smem[];
    float* tile = smem + SM_TILE;

    const int tid  = threadIdx.x;
    const int warp = tid >> 5;
    const int lane = tid & 31;
    const int nb   = warp >> 3;      // block within stage (0/1)
    const int ws   = warp & 7;
    const long row0 = (long)blockIdx.x * 32;

    const float* W1p[2] = {W1a, W1b};
    const float* W2p[2] = {W2a, W2b};
    const float* B1p[2] = {B1a, B1b};
    const float* B2p[2] = {B2a, B2b};

    // ---- stage weights for stage si into buffer (si&1) via cp.async ----
    auto stage = [&](int si) {
        const int layer = si >> 4, g = si & 15;
        float* wb = smem + SM_WB + (si & 1) * WBUF_STRIDE;
        u32 b = s2u(wb);
        const float* w1 = W1p[layer] + (size_t)g * 4096;
        const float* w2 = W2p[layer] + (size_t)g * 4096;
        cpa16(b + (u32)tid * 16u,          w1 + tid * 4);
        cpa16(b + (u32)(tid + 512) * 16u,  w1 + (tid + 512) * 4);
        cpa16(b + 16384u + (u32)tid * 16u,         w2 + tid * 4);
        cpa16(b + 16384u + (u32)(tid + 512) * 16u, w2 + (tid + 512) * 4);
        if (tid < 32)       cpa16(b + 32768u + (u32)tid * 16u, B1p[layer] + g * 128 + tid * 4);
        else if (tid < 48)  cpa16(b + 33280u + (u32)(tid - 32) * 16u, B2p[layer] + g * 64 + (tid - 32) * 4);
        asm volatile("cp.async.commit_group;");
    };

    stage(0);

    // ---- load x tile (coalesced float4) ----
    {
        const float4* src = (const float4*)(x + row0 * 1024);
        #pragma unroll
        for (int it = 0; it < 16; ++it) {
            int i = tid + it * NTHREADS;
            int r = i >> 8, c4 = i & 255;
            *(float4*)(tile + r * TS + c4 * 4) = src[r * 256 + c4];
        }
    }

    for (int si = 0; si < 32; ++si) {
        if (si == 16) {            // layer boundary: transpose tile in place
            __syncthreads();
            transpose_tile(tile, warp, lane);
        }
        if (si < 31) stage(si + 1);
        if (si < 31) asm volatile("cp.async.wait_group 1;");
        else         asm volatile("cp.async.wait_group 0;");
        __syncthreads();

        const float* wb    = smem + SM_WB + (si & 1) * WBUF_STRIDE;
        const int    cbase = ((si & 15) * 2 + nb) * 32;
        float*       hbb   = smem + SM_HB + nb * 2176;

        // ---- matmul1: 2 rows x 4 hidden per thread ----
        const int rh = lane >> 4;        // 0/1
        const int cg = lane & 15;        // hidden col group
        const int r0 = ws * 4 + rh * 2;
        u64 a00, a01, a10, a11;
        {
            const float* bp = wb + 8192 + nb * 64 + 4 * cg;
            a00 = *(const u64*)bp; a01 = *(const u64*)(bp + 2);
            a10 = a00; a11 = a01;
        }
        {
            const float* w1p = wb + nb * 2048 + 4 * cg;
            const float* xr  = tile + r0 * TS + cbase;
            #pragma unroll
            for (int kq = 0; kq < 8; ++kq) {
                float4 x0 = *(const float4*)(xr + 4 * kq);
                float4 x1 = *(const float4*)(xr + TS + 4 * kq);
                #pragma unroll
                for (int t = 0; t < 4; ++t) {
                    ulonglong2 wv = *(const ulonglong2*)(w1p + (4 * kq + t) * 64);
                    float xv0 = ((const float*)&x0)[t];
                    float xv1 = ((const float*)&x1)[t];
                    u64 xp0 = pack2(xv0, xv0);
                    u64 xp1 = pack2(xv1, xv1);
                    a00 = fma2(xp0, wv.x, a00);
                    a01 = fma2(xp0, wv.y, a01);
                    a10 = fma2(xp1, wv.x, a10);
                    a11 = fma2(xp1, wv.y, a11);
                }
            }
        }
        asm volatile("bar.sync %0, %1;" :: "r"(nb + 1), "r"(256) : "memory");

        // ---- ELU + stage h ----
        {
            float* hb = hbb + 4 * cg;
            u64 ar[2][2] = {{a00, a01}, {a10, a11}};
            #pragma unroll
            for (int i = 0; i < 2; ++i) {
                float e0, e1, e2, e3;
                unpack2(ar[i][0], e0, e1);
                unpack2(ar[i][1], e2, e3);
                float4 hv;
                hv.x = e0 > 0.f ? e0 : (__expf(e0) - 1.f);
                hv.y = e1 > 0.f ? e1 : (__expf(e1) - 1.f);
                hv.z = e2 > 0.f ? e2 : (__expf(e2) - 1.f);
                hv.w = e3 > 0.f ? e3 : (__expf(e3) - 1.f);
                *(float4*)(hb + (r0 + i) * HS) = hv;
            }
        }
        asm volatile("bar.sync %0, %1;" :: "r"(nb + 1), "r"(256) : "memory");

        // ---- matmul2: 1 row x 4 out cols per thread ----
        {
            const int rr = lane >> 3;    // 0..3
            const int c8 = lane & 7;     // col group
            const int r  = ws * 4 + rr;
            u64 b0, b1v;
            {
                const float* bp2 = wb + 8320 + nb * 32 + 4 * c8;
                u64 bb0 = *(const u64*)bp2;
                u64 bb1 = *(const u64*)(bp2 + 2);
                float4 rv = *(const float4*)(tile + r * TS + cbase + 4 * c8);
                const u64 ONE = pack2(1.f, 1.f);
                b0  = fma2(ONE, bb0, pack2(rv.x, rv.y));   // bias + residual
                b1v = fma2(ONE, bb1, pack2(rv.z, rv.w));
            }
            const float* hrd = hbb + r * HS;
            const float* w2p = wb + 4096 + nb * 2048 + 4 * c8;
            #pragma unroll
            for (int kq = 0; kq < 16; ++kq) {
                float4 hv = *(const float4*)(hrd + 4 * kq);
                #pragma unroll
                for (int t = 0; t < 4; ++t) {
                    ulonglong2 wv = *(const ulonglong2*)(w2p + (4 * kq + t) * 32);
                    float h = ((const float*)&hv)[t];
                    u64 hp = pack2(h, h);
                    b0  = fma2(hp, wv.x, b0);
                    b1v = fma2(hp, wv.y, b1v);
                }
            }
            float4 o;
            unpack2(b0, o.x, o.y);
            unpack2(b1v, o.z, o.w);
            *(float4*)(tile + r * TS + cbase + 4 * c8) = o;
        }
        __syncthreads();
    }

    transpose_tile(tile, warp, lane);     // undo layer-1 permutation
    __syncthreads();

    // ---- store output ----
    {
        float4* dst = (float4*)(out + row0 * 1024);
        #pragma unroll
        for (int it = 0; it < 16; ++it) {
            int i = tid + it * NTHREADS;
            int r = i >> 8, c4 = i & 255;
            dst[r * 256 + c4] = *(const float4*)(tile + r * TS + c4 * 4);
        }
    }
}

extern "C" void kernel_launch(void* const* d_in, const int* in_sizes, int n_in,
                              void* d_out, int out_size) {
    const float* x   = (const float*)d_in[0];
    const float* W1a = (const float*)d_in[1];
    const float* B1a = (const float*)d_in[2];
    const float* W2a = (const float*)d_in[3];
    const float* B2a = (const float*)d_in[4];
    const float* W1b = (const float*)d_in[5];
    const float* B1b = (const float*)d_in[6];
    const float* W2b = (const float*)d_in[7];
    const float* B2b = (const float*)d_in[8];
    float* out = (float*)d_out;

    int rows = in_sizes[0] / 1024;
    int grid = rows / 32;                 // 512

    size_t smem_bytes = (size_t)SM_TOTAL * sizeof(float);   // 217088 B
    static int configured = -1;
    if (configured < 0) {
        cudaFuncSetAttribute(mixer_kernel,
                             cudaFuncAttributeMaxDynamicSharedMemorySize,
                             (int)smem_bytes);
        configured = 1;
    }

    mixer_kernel<<<grid, NTHREADS, smem_bytes>>>(
        x, W1a, B1a, W2a, B2a, W1b, B1b, W2b, B2b, out);
}

// round 6
// speedup vs baseline: 1.7717x; 1.7717x over previous
#include <cuda_runtime.h>

#define NTHREADS 256
#define TS 1032                  // tile row stride (floats)
#define HS 68                    // hbuf row stride (floats)
#define W1S 72                   // w1 smem k-row stride (floats)
#define W2S 40                   // w2 smem k-row stride (floats)
#define W1BLK 2304               // per-block w1 slab (>= 32*72, also >= hbuf 32*68=2176)
#define W2BLK 2560               // per-block w2 slab (64*40)

// smem layout (float offsets)
#define SM_TILE 0
#define SM_W1   33024            // 32*1032
#define SM_W2   (SM_W1 + 4 * W1BLK)      // 42240
#define SM_B1   (SM_W2 + 4 * W2BLK)      // 52480
#define SM_B2   (SM_B1 + 256)            // 52736
#define SM_TOTAL (SM_B2 + 128)           // 52864 floats = 211456 B

typedef unsigned long long u64;
typedef unsigned int u32;

__device__ __forceinline__ u64 pack2(float lo, float hi) {
    u64 r; asm("mov.b64 %0, {%1, %2};" : "=l"(r) : "f"(lo), "f"(hi)); return r;
}
__device__ __forceinline__ void unpack2(u64 v, float& lo, float& hi) {
    asm("mov.b64 {%0, %1}, %2;" : "=f"(lo), "=f"(hi) : "l"(v));
}
__device__ __forceinline__ u32 s2u(const void* p) {
    u32 r;
    asm("{.reg .u64 t; cvta.to.shared.u64 t, %1; cvt.u32.u64 %0, t;}" : "=r"(r) : "l"(p));
    return r;
}
__device__ __forceinline__ void cpa16(u32 dst, const float* src) {
    asm volatile("cp.async.cg.shared.global [%0], [%1], 16;" :: "r"(dst), "l"(src));
}
__device__ __forceinline__ u32 f2tf(float f) {
    u32 u; asm("cvt.rna.tf32.f32 %0, %1;" : "=r"(u) : "f"(f)); return u;
}
__device__ __forceinline__ void split(float f, u32& h, u32& l) {
    h = f2tf(f);
    l = __float_as_uint(f - __uint_as_float(h));
}
__device__ __forceinline__ void mma8(float* c, const u32* a, const u32* b) {
    asm volatile(
        "mma.sync.aligned.m16n8k8.row.col.f32.tf32.tf32.f32 "
        "{%0,%1,%2,%3}, {%4,%5,%6,%7}, {%8,%9}, {%0,%1,%2,%3};"
        : "+f"(c[0]), "+f"(c[1]), "+f"(c[2]), "+f"(c[3])
        : "r"(a[0]), "r"(a[1]), "r"(a[2]), "r"(a[3]), "r"(b[0]), "r"(b[1]));
}
__device__ __forceinline__ float elu(float v) {
    return v > 0.f ? v : (__expf(v) - 1.f);
}

// in-place per-row 32x32 block transpose: row[32b+a] <-> row[32a+b]
__device__ __forceinline__ void transpose_tile(float* tile, int warp, int lane) {
    const int a2 = lane >> 3;     // 0..3
    const int B  = lane & 7;      // 0..7
    #pragma unroll
    for (int rr = 0; rr < 4; ++rr) {
        float* row = tile + (warp * 4 + rr) * TS;
        float4 v[2][4];
        #pragma unroll
        for (int h = 0; h < 2; ++h) {
            int A = a2 + 4 * h;
            #pragma unroll
            for (int i = 0; i < 4; ++i)
                v[h][i] = *(const float4*)(row + 32 * (4 * A + i) + 4 * B);
        }
        __syncwarp();
        #pragma unroll
        for (int h = 0; h < 2; ++h) {
            int A = a2 + 4 * h;
            #pragma unroll
            for (int i = 0; i < 4; ++i) {
                float4 t;
                t.x = ((const float*)&v[h][0])[i];
                t.y = ((const float*)&v[h][1])[i];
                t.z = ((const float*)&v[h][2])[i];
                t.w = ((const float*)&v[h][3])[i];
                *(float4*)(row + 32 * (4 * B + i) + 4 * A) = t;
            }
        }
        __syncwarp();
    }
}

__global__ __launch_bounds__(NTHREADS, 1) void mixer_kernel(
    const float* __restrict__ x,
    const float* __restrict__ W1a, const float* __restrict__ B1a,
    const float* __restrict__ W2a, const float* __restrict__ B2a,
    const float* __restrict__ W1b, const float* __restrict__ B1b,
    const float* __restrict__ W2b, const float* __restrict__ B2b,
    float* __restrict__ out)
{
    extern __shared__ float smem[];
    float* tile = smem + SM_TILE;
    float* w1s  = smem + SM_W1;
    float* w2s  = smem + SM_W2;
    float* b1s  = smem + SM_B1;
    float* b2s  = smem + SM_B2;

    const int tid  = threadIdx.x;
    const int warp = tid >> 5;
    const int lane = tid & 31;
    const int nb   = warp >> 1;          // block within group (0..3)
    const int mh   = warp & 1;           // row half (16 rows each)
    const int g    = lane >> 2;          // fragment group id (0..7)
    const int t4   = lane & 3;
    const int mbase = mh * 16;
    const int mrow  = mbase + g;
    const long row0 = (long)blockIdx.x * 32;

    const float* W1p[2] = {W1a, W1b};
    const float* W2p[2] = {W2a, W2b};
    const float* B1p[2] = {B1a, B1b};
    const float* B2p[2] = {B2a, B2b};

    // stage weights for group-iter si into the (single) weight buffer
    auto stage = [&](int si) {
        const int layer = si >> 3, gg = si & 7;
        const float* w1g = W1p[layer] + (size_t)gg * 4 * 2048;
        const float* w2g = W2p[layer] + (size_t)gg * 4 * 2048;
        #pragma unroll
        for (int j = 0; j < 8; ++j) {
            int c = tid + j * 256;
            int blk = c >> 9, r = c & 511;
            cpa16(s2u(w1s + blk * W1BLK + (r >> 4) * W1S + (r & 15) * 4),
                  w1g + blk * 2048 + r * 4);
            cpa16(s2u(w2s + blk * W2BLK + (r >> 3) * W2S + (r & 7) * 4),
                  w2g + blk * 2048 + r * 4);
        }
        if (tid < 64) {
            int blk = tid >> 4, i = tid & 15;
            cpa16(s2u(b1s + blk * 64 + i * 4), B1p[layer] + (gg * 4 + blk) * 64 + i * 4);
        } else if (tid < 96) {
            int t = tid - 64, blk = t >> 3, i = t & 7;
            cpa16(s2u(b2s + blk * 32 + i * 4), B2p[layer] + (gg * 4 + blk) * 32 + i * 4);
        }
        asm volatile("cp.async.commit_group;");
    };

    stage(0);

    // load x tile (coalesced float4)
    {
        const float4* src = (const float4*)(x + row0 * 1024);
        #pragma unroll
        for (int it = 0; it < 32; ++it) {
            int i = tid + it * NTHREADS;
            int r = i >> 8, c4 = i & 255;
            *(float4*)(tile + r * TS + c4 * 4) = src[r * 256 + c4];
        }
    }

    for (int gi = 0; gi < 16; ++gi) {
        if (gi == 8) transpose_tile(tile, warp, lane);   // layer boundary

        asm volatile("cp.async.wait_group 0;");
        __syncthreads();

        const int cbase = ((gi & 7) * 4 + nb) * 32;
        const float* w1p = w1s + nb * W1BLK;
        const float* w2p = w2s + nb * W2BLK;
        float*       hb  = w1s + nb * W1BLK;   // alias (after named bar)

        // ================= matmul1: 16 rows x 64 hidden =================
        u32 ah[4][4], al[4][4];
        {
            const float* xr = tile + mrow * TS + cbase;
            #pragma unroll
            for (int kt = 0; kt < 4; ++kt) {
                split(xr[kt * 8 + t4],            ah[kt][0], al[kt][0]);
                split(xr[8 * TS + kt * 8 + t4],   ah[kt][1], al[kt][1]);
                split(xr[kt * 8 + t4 + 4],        ah[kt][2], al[kt][2]);
                split(xr[8 * TS + kt * 8 + t4 + 4], ah[kt][3], al[kt][3]);
            }
        }
        float c1[8][4];
        {
            const float* b1p = b1s + nb * 64;
            #pragma unroll
            for (int nt = 0; nt < 8; ++nt) {
                float blo, bhi;
                unpack2(*(const u64*)(b1p + nt * 8 + 2 * t4), blo, bhi);
                c1[nt][0] = blo; c1[nt][1] = bhi; c1[nt][2] = blo; c1[nt][3] = bhi;
            }
        }
        #pragma unroll
        for (int nt = 0; nt < 8; ++nt) {
            #pragma unroll
            for (int kt = 0; kt < 4; ++kt) {
                u32 bh[2], bl[2];
                split(w1p[(kt * 8 + t4) * W1S + nt * 8 + g],     bh[0], bl[0]);
                split(w1p[(kt * 8 + t4 + 4) * W1S + nt * 8 + g], bh[1], bl[1]);
                mma8(c1[nt], ah[kt], bh);
                mma8(c1[nt], al[kt], bh);
                mma8(c1[nt], ah[kt], bl);
            }
        }
        // partner warp must finish reading w1 before we overwrite it with h
        asm volatile("bar.sync %0, 64;" :: "r"(nb + 1) : "memory");

        // ================= ELU + stage h =================
        #pragma unroll
        for (int nt = 0; nt < 8; ++nt) {
            float e0 = elu(c1[nt][0]), e1 = elu(c1[nt][1]);
            float e2 = elu(c1[nt][2]), e3 = elu(c1[nt][3]);
            *(u64*)(hb + mrow * HS + nt * 8 + 2 * t4)       = pack2(e0, e1);
            *(u64*)(hb + (mrow + 8) * HS + nt * 8 + 2 * t4) = pack2(e2, e3);
        }
        __syncwarp();

        // ================= matmul2: 16 rows x 32 out (+bias+residual) =================
        float c2[4][4];
        {
            const float* b2p  = b2s + nb * 32;
            const float* resp = tile + mrow * TS + cbase;
            #pragma unroll
            for (int nt = 0; nt < 4; ++nt) {
                float blo, bhi, r0l, r0h, r1l, r1h;
                unpack2(*(const u64*)(b2p + nt * 8 + 2 * t4), blo, bhi);
                unpack2(*(const u64*)(resp + nt * 8 + 2 * t4), r0l, r0h);
                unpack2(*(const u64*)(resp + 8 * TS + nt * 8 + 2 * t4), r1l, r1h);
                c2[nt][0] = blo + r0l; c2[nt][1] = bhi + r0h;
                c2[nt][2] = blo + r1l; c2[nt][3] = bhi + r1h;
            }
        }
        #pragma unroll
        for (int kt = 0; kt < 8; ++kt) {
            u32 ah2[4], al2[4];
            split(hb[mrow * HS + kt * 8 + t4],            ah2[0], al2[0]);
            split(hb[(mrow + 8) * HS + kt * 8 + t4],      ah2[1], al2[1]);
            split(hb[mrow * HS + kt * 8 + t4 + 4],        ah2[2], al2[2]);
            split(hb[(mrow + 8) * HS + kt * 8 + t4 + 4],  ah2[3], al2[3]);
            #pragma unroll
            for (int nt = 0; nt < 4; ++nt) {
                u32 bh[2], bl[2];
                split(w2p[(kt * 8 + t4) * W2S + nt * 8 + g],     bh[0], bl[0]);
                split(w2p[(kt * 8 + t4 + 4) * W2S + nt * 8 + g], bh[1], bl[1]);
                mma8(c2[nt], ah2, bh);
                mma8(c2[nt], al2, bh);
                mma8(c2[nt], ah2, bl);
            }
        }
        {
            float* resp = tile + mrow * TS + cbase;
            #pragma unroll
            for (int nt = 0; nt < 4; ++nt) {
                *(u64*)(resp + nt * 8 + 2 * t4)          = pack2(c2[nt][0], c2[nt][1]);
                *(u64*)(resp + 8 * TS + nt * 8 + 2 * t4) = pack2(c2[nt][2], c2[nt][3]);
            }
        }

        __syncthreads();                       // all weight reads done
        if (gi < 15) stage(gi + 1);            // refill single buffer
    }

    transpose_tile(tile, warp, lane);          // undo layer-1 permutation
    __syncthreads();

    // store output (coalesced float4)
    {
        float4* dst = (float4*)(out + row0 * 1024);
        #pragma unroll
        for (int it = 0; it < 32; ++it) {
            int i = tid + it * NTHREADS;
            int r = i >> 8, c4 = i & 255;
            dst[r * 256 + c4] = *(const float4*)(tile + r * TS + c4 * 4);
        }
    }
}

extern "C" void kernel_launch(void* const* d_in, const int* in_sizes, int n_in,
                              void* d_out, int out_size) {
    const float* x   = (const float*)d_in[0];
    const float* W1a = (const float*)d_in[1];
    const float* B1a = (const float*)d_in[2];
    const float* W2a = (const float*)d_in[3];
    const float* B2a = (const float*)d_in[4];
    const float* W1b = (const float*)d_in[5];
    const float* B1b = (const float*)d_in[6];
    const float* W2b = (const float*)d_in[7];
    const float* B2b = (const float*)d_in[8];
    float* out = (float*)d_out;

    int rows = in_sizes[0] / 1024;
    int grid = rows / 32;                       // 512

    size_t smem_bytes = (size_t)SM_TOTAL * sizeof(float);   // 211456 B
    static int configured = -1;
    if (configured < 0) {
        cudaFuncSetAttribute(mixer_kernel,
                             cudaFuncAttributeMaxDynamicSharedMemorySize,
                             (int)smem_bytes);
        configured = 1;
    }

    mixer_kernel<<<grid, NTHREADS, smem_bytes>>>(
        x, W1a, B1a, W2a, B2a, W1b, B1b, W2b, B2b, out);
}